// round 16
// baseline (speedup 1.0000x reference)
#include <cuda_runtime.h>
#include <cuda_fp16.h>
#include <cstdint>

#define NB 4096
#define NC 64
#define DD 32
#define KK 1024   // H1*H2

// ---------------------------------------------------------------- W fragments
// K matrix pre-converted to fp16, per mma.m16n8k16 A-fragment:
// g_Wf16[ch(64)][mt(4)][lane(32)] = uint4 {a0,a1,a2,a3} (each fp16x2).
// Padded by 2 chunks so the register prefetch's tail loads stay in-bounds.
__device__ __align__(16) uint4 g_Wf16[66 * 4 * 32];

__global__ void wfrag_kernel(const float* __restrict__ K) {
    int idx = blockIdx.x * blockDim.x + threadIdx.x;  // 8192
    int lane = idx & 31, mt = (idx >> 5) & 3, ch = idx >> 7;
    int r0 = 16 * mt + (lane >> 2);
    int k0 = 16 * ch + 2 * (lane & 3);
    uint32_t q[4];
#pragma unroll
    for (int u = 0; u < 4; u++) {
        int r = r0 + (u & 1) * 8;
        int k = k0 + (u >> 1) * 8;
        __half2 h = __floats2half2_rn(K[r * KK + k], K[r * KK + k + 1]);
        q[u] = *(uint32_t*)&h;
    }
    g_Wf16[idx] = make_uint4(q[0], q[1], q[2], q[3]);
}

// ---------------------------------------------------------------- helpers
__device__ __forceinline__ uint32_t f16x2_of(float hi, float lo) {
    uint32_t r;
    asm("cvt.rn.f16x2.f32 %0, %1, %2;" : "=r"(r) : "f"(hi), "f"(lo));
    return r;
}
__device__ __forceinline__ uint32_t hmul2(uint32_t a, uint32_t b) {
    uint32_t r;
    asm("mul.f16x2 %0, %1, %2;" : "=r"(r) : "r"(a), "r"(b));
    return r;
}
// fp16-accumulate HMMA: D (2x f16x2 regs) += A * B
__device__ __forceinline__ void mma_f16d(uint32_t& d0, uint32_t& d1,
                                         uint32_t a0, uint32_t a1, uint32_t a2,
                                         uint32_t a3, uint32_t b0, uint32_t b1) {
    asm volatile(
        "mma.sync.aligned.m16n8k16.row.col.f16.f16.f16.f16 "
        "{%0,%1}, {%2,%3,%4,%5}, {%6,%7}, {%0,%1};"
        : "+r"(d0), "+r"(d1)
        : "r"(a0), "r"(a1), "r"(a2), "r"(a3), "r"(b0), "r"(b1));
}

// ---------------------------------------------------------------- main kernel
// CTA: 128 threads = 4 warps = 2 batches; 2 warps per batch (m-split):
// warp (w&1) covers m-tiles {2*(w&1), 2*(w&1)+1} for all 32 d-columns.
// Per-batch GEMM: OUT[c(64), d(32)] = W[c,k] * Z[k,d], K=1024, fp16 1-pass.
// NEW: MMAs accumulate into fp16 D over a 4-chunk (64-k) window, then the
// window is drained into f32 accumulators (tests whether the legacy-HMMA
// rate doubles without the f32 accumulator). W read by plain LDG.128
// (L1-resident) with a 2-chunk register double buffer; x pre-splatted to
// f16x2 in SMEM ([i][g][nf], one broadcast LDS.128 per i).
__global__ __launch_bounds__(128, 5)
void cin_mma_kernel(const float* __restrict__ X, const float* __restrict__ Y,
                    float* __restrict__ out_mat, float* __restrict__ out_fin) {
    // x_q[bl][i][g][nf] = splat f16x2 of x[b, i, g + 8*nf]; i padded to 33
    __shared__ uint32_t x_q[2][33][8][4];          // 8448 B

    const int t = threadIdx.x;
    const int lane = t & 31;
    const int w = t >> 5;
    const int bl = w >> 1;            // local batch 0..1
    const int mh = w & 1;             // m-half: m-tiles {2*mh, 2*mh+1}
    const int b = blockIdx.x * 2 + bl;
    const int g = lane >> 2;          // row group / d offset
    const int jm = lane & 3;

    // stage x pre-splatted (each thread: 16 values, coalesced float4 loads)
    {
        const float4* xg = (const float4*)(X + (size_t)blockIdx.x * 2 * KK);
#pragma unroll
        for (int rep = 0; rep < 4; rep++) {
            int idx4 = rep * 128 + t;          // 0..511 float4s
            float4 v = xg[idx4];
            int e0 = idx4 * 4;                 // element index (b_l,i,d)
            int b_l = e0 >> 10;
            int i = (e0 >> 5) & 31;
            int d0 = e0 & 31;
            const float vv[4] = {v.x, v.y, v.z, v.w};
#pragma unroll
            for (int u = 0; u < 4; u++) {
                int d = d0 + u;
                x_q[b_l][i][d & 7][d >> 3] = f16x2_of(vv[u], vv[u]);
            }
        }
    }
    __syncthreads();

    // y pre-packed f16x2. B frag (n8k16 col): b0 <- klocal {2jm, 2jm+1},
    // b1 <- {2jm+8, 2jm+9}; j = p*16 + klocal; d = g + 8*nf.
    const float* yb = Y + (size_t)b * KK;
    uint32_t y2[4][4];
#pragma unroll
    for (int nf = 0; nf < 4; nf++) {
        int d = g + 8 * nf;
#pragma unroll
        for (int p = 0; p < 2; p++) {
            y2[nf][2 * p] = f16x2_of(yb[(16 * p + 2 * jm + 1) * 32 + d],
                                     yb[(16 * p + 2 * jm) * 32 + d]);
            y2[nf][2 * p + 1] = f16x2_of(yb[(16 * p + 8 + 2 * jm + 1) * 32 + d],
                                         yb[(16 * p + 8 + 2 * jm) * 32 + d]);
        }
    }

    float acc[2][4][4];               // f32 master accumulators
#pragma unroll
    for (int m = 0; m < 2; m++)
#pragma unroll
        for (int n = 0; n < 4; n++)
#pragma unroll
            for (int q = 0; q < 4; q++) acc[m][n][q] = 0.0f;

    uint32_t accd[2][4][2];           // fp16 window accumulators (f16x2 regs)
#pragma unroll
    for (int m = 0; m < 2; m++)
#pragma unroll
        for (int n = 0; n < 4; n++) { accd[m][n][0] = 0u; accd[m][n][1] = 0u; }

    // W source pointer; chunk c, mtile m: gw[c*128 + m*32]
    const uint4* gw = g_Wf16 + (2 * mh) * 32 + lane;
    const uint4* xq = (const uint4*)&x_q[bl][0][g][0];

    // register double buffer, prefetch distance 2 chunks
    uint4 abuf[2][2];
    abuf[0][0] = gw[0];   abuf[0][1] = gw[32];
    abuf[1][0] = gw[128]; abuf[1][1] = gw[160];
    uint4 xv = xq[0];     // splatted x for i=0, all 4 nf

#pragma unroll 4
    for (int ch = 0; ch < 64; ch++) {
        const int p = ch & 1;
        const int i = ch >> 1;

        // B fragments: bf[nf][r] = xsplat[nf] * y2[nf][2p+r]   (HMUL2)
        const uint32_t xs[4] = {xv.x, xv.y, xv.z, xv.w};
        uint32_t bf[4][2];
#pragma unroll
        for (int nf = 0; nf < 4; nf++) {
            bf[nf][0] = hmul2(xs[nf], y2[nf][2 * p]);
            bf[nf][1] = hmul2(xs[nf], y2[nf][2 * p + 1]);
        }

#pragma unroll
        for (int nf = 0; nf < 4; nf++) {
            mma_f16d(accd[0][nf][0], accd[0][nf][1],
                     abuf[p][0].x, abuf[p][0].y, abuf[p][0].z, abuf[p][0].w,
                     bf[nf][0], bf[nf][1]);
            mma_f16d(accd[1][nf][0], accd[1][nf][1],
                     abuf[p][1].x, abuf[p][1].y, abuf[p][1].z, abuf[p][1].w,
                     bf[nf][0], bf[nf][1]);
        }

        // refill this parity's buffer with chunk ch+2 (padded: always safe)
        abuf[p][0] = gw[(ch + 2) * 128];
        abuf[p][1] = gw[(ch + 2) * 128 + 32];
        if (p == 1) xv = xq[(i + 1) * 8];   // next i's x (padded row 32)

        // drain the fp16 window into f32 every 4 chunks (compile-time pred)
        if ((ch & 3) == 3) {
#pragma unroll
            for (int m = 0; m < 2; m++)
#pragma unroll
                for (int nf = 0; nf < 4; nf++) {
                    float2 lo = __half22float2(*(__half2*)&accd[m][nf][0]);
                    float2 hi = __half22float2(*(__half2*)&accd[m][nf][1]);
                    acc[m][nf][0] += lo.x;
                    acc[m][nf][1] += lo.y;
                    acc[m][nf][2] += hi.x;
                    acc[m][nf][3] += hi.y;
                    accd[m][nf][0] = 0u;
                    accd[m][nf][1] = 0u;
                }
        }
    }

    // ----- epilogue: D frag rows c = 16*(2*mh+m) + g (+8),
    // cols d = 8*nf + 2*jm + {0,1}. Each warp owns distinct c rows.
    float* om = out_mat + (size_t)b * (NC * DD);
    float* fb = out_fin + (size_t)b * NC;
#pragma unroll
    for (int m = 0; m < 2; m++) {
        const int c0 = 16 * (2 * mh + m) + g;
        float s0 = 0.0f, s1 = 0.0f;
#pragma unroll
        for (int nf = 0; nf < 4; nf++) {
            int d0 = 8 * nf + 2 * jm;
            *(float2*)&om[c0 * DD + d0] =
                make_float2(acc[m][nf][0], acc[m][nf][1]);
            *(float2*)&om[(c0 + 8) * DD + d0] =
                make_float2(acc[m][nf][2], acc[m][nf][3]);
            s0 += acc[m][nf][0] + acc[m][nf][1];
            s1 += acc[m][nf][2] + acc[m][nf][3];
        }
        // sum across the quad (lanes sharing g): covers all 32 d
#pragma unroll
        for (int o = 1; o <= 2; o <<= 1) {
            s0 += __shfl_xor_sync(0xffffffffu, s0, o);
            s1 += __shfl_xor_sync(0xffffffffu, s1, o);
        }
        if (jm == 0) { fb[c0] = s0; fb[c0 + 8] = s1; }
    }
}

extern "C" void kernel_launch(void* const* d_in, const int* in_sizes, int n_in,
                              void* d_out, int out_size) {
    const float* X = (const float*)d_in[0];
    const float* Y = (const float*)d_in[1];
    const float* K = (const float*)d_in[2];
    float* om = (float*)d_out;
    float* fin = om + (size_t)NB * NC * DD;

    wfrag_kernel<<<32, 256>>>(K);
    cin_mma_kernel<<<NB / 2, 128>>>(X, Y, om, fin);
}

// round 17
// speedup vs baseline: 1.2030x; 1.2030x over previous
#include <cuda_runtime.h>
#include <cuda_fp16.h>
#include <cstdint>

#define NB 4096
#define NC 64
#define DD 32
#define KK 1024   // H1*H2

// ---------------------------------------------------------------- W fragments
// K matrix pre-converted to fp16, per mma.m16n8k16 A-fragment:
// g_Wf16[ch(64)][mt(4)][lane(32)] = uint4 {a0,a1,a2,a3} (each fp16x2).
// a0=(r, k0|k0+1) a1=(r+8, ..) a2=(r, k0+8|k0+9) a3=(r+8, ..),
// r = 16*mt + lane/4, k0 = 2*(lane%4); global k = 16*ch + klocal.
__device__ __align__(16) uint4 g_Wf16[64 * 4 * 32];

__global__ void wfrag_kernel(const float* __restrict__ K) {
    int idx = blockIdx.x * blockDim.x + threadIdx.x;  // 8192
    int lane = idx & 31, mt = (idx >> 5) & 3, ch = idx >> 7;
    int r0 = 16 * mt + (lane >> 2);
    int k0 = 16 * ch + 2 * (lane & 3);
    uint32_t q[4];
#pragma unroll
    for (int u = 0; u < 4; u++) {
        int r = r0 + (u & 1) * 8;
        int k = k0 + (u >> 1) * 8;
        __half2 h = __floats2half2_rn(K[r * KK + k], K[r * KK + k + 1]);
        q[u] = *(uint32_t*)&h;
    }
    g_Wf16[idx] = make_uint4(q[0], q[1], q[2], q[3]);
}

// ---------------------------------------------------------------- helpers
__device__ __forceinline__ uint32_t f16x2_of(float hi, float lo) {
    uint32_t r;
    asm("cvt.rn.f16x2.f32 %0, %1, %2;" : "=r"(r) : "f"(hi), "f"(lo));
    return r;
}
__device__ __forceinline__ uint32_t hmul2(uint32_t a, uint32_t b) {
    uint32_t r;
    asm("mul.f16x2 %0, %1, %2;" : "=r"(r) : "r"(a), "r"(b));
    return r;
}
__device__ __forceinline__ void mma_f16(float& c0, float& c1, float& c2, float& c3,
                                        uint32_t a0, uint32_t a1, uint32_t a2,
                                        uint32_t a3, uint32_t b0, uint32_t b1) {
    asm volatile(
        "mma.sync.aligned.m16n8k16.row.col.f32.f16.f16.f32 "
        "{%0,%1,%2,%3}, {%4,%5,%6,%7}, {%8,%9}, {%0,%1,%2,%3};"
        : "+f"(c0), "+f"(c1), "+f"(c2), "+f"(c3)
        : "r"(a0), "r"(a1), "r"(a2), "r"(a3), "r"(b0), "r"(b1));
}

// ---------------------------------------------------------------- main kernel
// CTA: 64 threads = 2 warps = 2 batches. ONE warp per batch, covering the
// whole per-batch GEMM OUT[c(64), d(32)] = W[c,k]*Z[k,d] (K=1024, fp16
// single pass). Per k16-chunk: ONE B-build (8 HMUL2) + 4 A-fragment
// LDG.128 (L1-resident W) -> 16 MMAs. Small CTAs (grid 2048, 8 CTAs/SM)
// halve the end-of-grid straggler tail vs 128-thread CTAs; y is staged
// through SMEM so its scattered reads are LDS, not DRAM.
__global__ __launch_bounds__(64, 8)
void cin_mma_kernel(const float* __restrict__ X, const float* __restrict__ Y,
                    float* __restrict__ out_mat, float* __restrict__ out_fin) {
    __shared__ uint32_t x_q[2][32][8][4];   // 8 KB: splat f16x2 of x[b,i,d]
    __shared__ float y_s[2][KK];            // 8 KB: y for the CTA's 2 batches

    const int t = threadIdx.x;
    const int lane = t & 31;
    const int w = t >> 5;             // local batch 0..1
    const int b = blockIdx.x * 2 + w;
    const int g = lane >> 2;          // row group / d offset
    const int jm = lane & 3;

    // stage x pre-splatted + y raw (both coalesced float4)
    {
        const float4* xg = (const float4*)(X + (size_t)blockIdx.x * 2 * KK);
        const float4* yg = (const float4*)(Y + (size_t)blockIdx.x * 2 * KK);
        float4* ys4 = (float4*)y_s;
#pragma unroll
        for (int rep = 0; rep < 8; rep++) {
            int idx4 = rep * 64 + t;           // 0..511 float4s
            float4 v = xg[idx4];
            ys4[idx4] = yg[idx4];
            int e0 = idx4 * 4;                 // element index (b_l,i,d)
            int b_l = e0 >> 10;
            int i = (e0 >> 5) & 31;
            int d0 = e0 & 31;
            const float vv[4] = {v.x, v.y, v.z, v.w};
#pragma unroll
            for (int u = 0; u < 4; u++) {
                int d = d0 + u;
                x_q[b_l][i][d & 7][d >> 3] = f16x2_of(vv[u], vv[u]);
            }
        }
    }
    __syncthreads();

    // y pre-packed f16x2 (reads from SMEM). B frag (n8k16 col):
    // b0 <- klocal {2jm, 2jm+1}, b1 <- {2jm+8, 2jm+9}; j = p*16 + klocal;
    // d = g + 8*nf.
    const float* yb = y_s[w];
    uint32_t y2[4][4];
#pragma unroll
    for (int nf = 0; nf < 4; nf++) {
        int d = g + 8 * nf;
#pragma unroll
        for (int p = 0; p < 2; p++) {
            y2[nf][2 * p] = f16x2_of(yb[(16 * p + 2 * jm + 1) * 32 + d],
                                     yb[(16 * p + 2 * jm) * 32 + d]);
            y2[nf][2 * p + 1] = f16x2_of(yb[(16 * p + 8 + 2 * jm + 1) * 32 + d],
                                         yb[(16 * p + 8 + 2 * jm) * 32 + d]);
        }
    }

    float acc[4][4][4];   // [mt][nf][q]
#pragma unroll
    for (int m = 0; m < 4; m++)
#pragma unroll
        for (int n = 0; n < 4; n++)
#pragma unroll
            for (int q = 0; q < 4; q++) acc[m][n][q] = 0.0f;

    // W pointer: chunk ch, mtile mt -> gw[ch*128 + mt*32]
    const uint4* gw = g_Wf16 + lane;
    const uint4* xq = (const uint4*)&x_q[w][0][g][0];

    uint4 xv = xq[0];

#pragma unroll 2
    for (int ch = 0; ch < 64; ch++) {
        const int p = ch & 1;
        const int i = ch >> 1;

        // A fragments for all 4 m-tiles (fresh regs each iter; ptxas
        // pipelines these L1-hit loads across the unrolled iterations)
        uint4 a0 = gw[ch * 128];
        uint4 a1 = gw[ch * 128 + 32];
        uint4 a2 = gw[ch * 128 + 64];
        uint4 a3 = gw[ch * 128 + 96];

        // ONE B-build for the chunk: bf[nf][r] = xsplat[nf]*y2[nf][2p+r]
        const uint32_t xs[4] = {xv.x, xv.y, xv.z, xv.w};
        uint32_t bf[4][2];
#pragma unroll
        for (int nf = 0; nf < 4; nf++) {
            bf[nf][0] = hmul2(xs[nf], y2[nf][2 * p]);
            bf[nf][1] = hmul2(xs[nf], y2[nf][2 * p + 1]);
        }
        if (p == 1 && i < 31) xv = xq[(i + 1) * 8];   // next i's x

        // 16 MMAs
#pragma unroll
        for (int nf = 0; nf < 4; nf++) {
            mma_f16(acc[0][nf][0], acc[0][nf][1], acc[0][nf][2], acc[0][nf][3],
                    a0.x, a0.y, a0.z, a0.w, bf[nf][0], bf[nf][1]);
            mma_f16(acc[1][nf][0], acc[1][nf][1], acc[1][nf][2], acc[1][nf][3],
                    a1.x, a1.y, a1.z, a1.w, bf[nf][0], bf[nf][1]);
            mma_f16(acc[2][nf][0], acc[2][nf][1], acc[2][nf][2], acc[2][nf][3],
                    a2.x, a2.y, a2.z, a2.w, bf[nf][0], bf[nf][1]);
            mma_f16(acc[3][nf][0], acc[3][nf][1], acc[3][nf][2], acc[3][nf][3],
                    a3.x, a3.y, a3.z, a3.w, bf[nf][0], bf[nf][1]);
        }
    }

    // ----- epilogue: D frag rows c = 16*mt + g (+8),
    // cols d = 8*nf + 2*jm + {0,1}. One warp owns the whole batch.
    float* om = out_mat + (size_t)b * (NC * DD);
    float* fb = out_fin + (size_t)b * NC;
#pragma unroll
    for (int mt = 0; mt < 4; mt++) {
        const int c0 = 16 * mt + g;
        float s0 = 0.0f, s1 = 0.0f;
#pragma unroll
        for (int nf = 0; nf < 4; nf++) {
            int d0 = 8 * nf + 2 * jm;
            *(float2*)&om[c0 * DD + d0] =
                make_float2(acc[mt][nf][0], acc[mt][nf][1]);
            *(float2*)&om[(c0 + 8) * DD + d0] =
                make_float2(acc[mt][nf][2], acc[mt][nf][3]);
            s0 += acc[mt][nf][0] + acc[mt][nf][1];
            s1 += acc[mt][nf][2] + acc[mt][nf][3];
        }
        // sum across the quad (lanes sharing g): covers all 32 d
#pragma unroll
        for (int o = 1; o <= 2; o <<= 1) {
            s0 += __shfl_xor_sync(0xffffffffu, s0, o);
            s1 += __shfl_xor_sync(0xffffffffu, s1, o);
        }
        if (jm == 0) { fb[c0] = s0; fb[c0 + 8] = s1; }
    }
}

extern "C" void kernel_launch(void* const* d_in, const int* in_sizes, int n_in,
                              void* d_out, int out_size) {
    const float* X = (const float*)d_in[0];
    const float* Y = (const float*)d_in[1];
    const float* K = (const float*)d_in[2];
    float* om = (float*)d_out;
    float* fin = om + (size_t)NB * NC * DD;

    wfrag_kernel<<<32, 256>>>(K);
    cin_mma_kernel<<<NB / 2, 64>>>(X, Y, om, fin);
}